// round 12
// baseline (speedup 1.0000x reference)
#include <cuda_runtime.h>
#include <cuda_fp16.h>
#include <math.h>

#define N_INST 16384
#define NB1    1024
#define NB2    64
#define DIM    1024
#define NATT   256
#define NCLS   512

// ---------------- scratch (device globals; no allocation allowed) ----------
__device__ float g_emb1[N_INST * DIM];   // 64 MB (fp32 for segsum accuracy)
__device__ float g_emb2[NB1 * DIM];
__device__ float g_emb3[NB2 * DIM];
__device__ float g_s[N_INST + NB1 + NB2];
__device__ float g_stats[8];
// conv2 weights, transposed [n=64][k=800], fp16
__device__ __half g_w2t[64 * 800];
// embeddings as fp16 (A-side of attention GEMMs)
__device__ __half g_emb1f16[N_INST * DIM];
__device__ __half g_emb2f16[NB1 * DIM];
__device__ __half g_emb3f16[NB2 * DIM];
// attention weights, transposed [n=256][k=1024], fp16, 3 levels
__device__ __half g_awt[3 * NATT * DIM];

__device__ __forceinline__ float* emb_buf(int lvl) {
    return lvl == 0 ? g_emb1 : (lvl == 1 ? g_emb2 : g_emb3);
}
__device__ __forceinline__ float* s_buf(int lvl) {
    return lvl == 0 ? g_s : (lvl == 1 ? g_s + N_INST : g_s + N_INST + NB1);
}

// ---------------- mma helpers ----------------------------------------------
__device__ __forceinline__ void ldsm4(unsigned& r0, unsigned& r1, unsigned& r2,
                                      unsigned& r3, unsigned a) {
    asm volatile("ldmatrix.sync.aligned.m8n8.x4.shared.b16 {%0,%1,%2,%3}, [%4];"
                 : "=r"(r0), "=r"(r1), "=r"(r2), "=r"(r3) : "r"(a));
}
__device__ __forceinline__ void mma_f16(float* c, unsigned a0, unsigned a1,
                                        unsigned a2, unsigned a3,
                                        unsigned b0, unsigned b1) {
    asm volatile(
        "mma.sync.aligned.m16n8k16.row.col.f32.f16.f16.f32 "
        "{%0,%1,%2,%3},{%4,%5,%6,%7},{%8,%9},{%0,%1,%2,%3};"
        : "+f"(c[0]), "+f"(c[1]), "+f"(c[2]), "+f"(c[3])
        : "r"(a0), "r"(a1), "r"(a2), "r"(a3), "r"(b0), "r"(b1));
}

// ---------------------------------------------------------------------------
// Prep kernels: weight transposes to fp16
// ---------------------------------------------------------------------------
__global__ __launch_bounds__(256) void prep_w2t(const float* __restrict__ w2) {
    const int idx = blockIdx.x * 256 + threadIdx.x;
    if (idx >= 64 * 800) return;
    const int n = idx / 800, k = idx - n * 800;
    g_w2t[idx] = __float2half(w2[k * 64 + n]);
}

__global__ __launch_bounds__(256) void prep_awt_all(
    const float* __restrict__ W0, const float* __restrict__ W1,
    const float* __restrict__ W2)
{
    const int gidx = blockIdx.x * 256 + threadIdx.x;   // 3*262144
    const int set = gidx >> 18;
    const int idx = gidx & 262143;
    const float* W = set == 0 ? W0 : (set == 1 ? W1 : W2);
    const int n = idx >> 10, k = idx & 1023;
    g_awt[set * (NATT * DIM) + idx] = __float2half(W[k * NATT + n]);
}

// ---------------------------------------------------------------------------
// Fused conv kernel: one CTA = 2 images; 2 CTAs/SM.
// Phase A: conv1 + relu + pool via HFMA2 (dx pool-pair packed in half2 lanes).
//   Input staged as fp16 twice: aligned copy + 1-shifted copy so every
//   (kx parity) pair load is a 4B-aligned LDS.32.
// Phase B: conv2 implicit GEMM, single-term fp16 mma (unchanged from R11).
// smem: p1[2 img][144*40 fp16] @0 (23040)
//       staging @23040: PhaseA w1d(3200)+b1(128)+in16(3136)+sh16(3136)
//                     | PhaseB slab 21504 B
// ---------------------------------------------------------------------------
#define FC_SMEM 44544

__global__ __launch_bounds__(256, 2) void fused_conv_kernel(
    const float* __restrict__ x,
    const float* __restrict__ w1, const float* __restrict__ b1,
    const float* __restrict__ b2)
{
    extern __shared__ char smem[];
    const unsigned sbase = (unsigned)__cvta_generic_to_shared(smem);
    const int tid = threadIdx.x;

    __half* p1 = (__half*)smem;             // [img][144*40]

    // ---------------- Phase A: conv1 + relu + pool (HFMA2) ----------------
    {
        __half2* w1d = (__half2*)(smem + 23040);   // [tap][ch] dup pairs, 800
        float*   b1_s = (float*)(smem + 26240);    // 32
        __half*  in16 = (__half*)(smem + 26368);   // [img][784] aligned copy
        __half*  sh16 = (__half*)(smem + 29504);   // [img][784] shifted by 1

        for (int i = tid; i < 800; i += 256) {
            const __half h = __float2half(w1[i]);
            w1d[i] = __halves2half2(h, h);
        }
        if (tid < 32) b1_s[tid] = b1[tid];
        const float* x0 = x + (size_t)blockIdx.x * 2 * 784;
        for (int i = tid; i < 1568; i += 256) {
            in16[i] = __float2half(x0[i]);
            const int c = i % 28;
            sh16[i] = (c < 27) ? __float2half(x0[i + 1]) : __float2half(0.f);
        }
        __syncthreads();

        for (int t = tid; t < 2304; t += 256) {
            const int img = t >= 1152;
            const int tt  = t - img * 1152;
            const int c0 = (tt & 7) * 4;
            const int p  = tt >> 3;
            const int pr = p / 12, pc = p % 12;
            const int y0 = pr * 2, xc = pc * 2;
            const __half* inb = in16 + img * 784;
            const __half* shb = sh16 + img * 784;

            __half2 acc[2][4];                  // [dy][ch], lanes = dx pair
            #pragma unroll
            for (int d = 0; d < 2; d++)
                #pragma unroll
                for (int ch = 0; ch < 4; ch++)
                    acc[d][ch] = __float2half2_rn(0.f);

            #pragma unroll
            for (int ky = 0; ky < 5; ky++) {
                const int r0 = (y0 + ky) * 28;
                const int r1 = r0 + 28;
                #pragma unroll
                for (int kx = 0; kx < 5; kx++) {
                    union { uint4 u; __half2 h[4]; } wv;
                    wv.u = *(const uint4*)&w1d[(ky * 5 + kx) * 32 + c0];
                    __half2 iv0, iv1;
                    if (kx & 1) {
                        iv0 = *(const __half2*)&shb[r0 + xc + kx - 1];
                        iv1 = *(const __half2*)&shb[r1 + xc + kx - 1];
                    } else {
                        iv0 = *(const __half2*)&inb[r0 + xc + kx];
                        iv1 = *(const __half2*)&inb[r1 + xc + kx];
                    }
                    #pragma unroll
                    for (int ch = 0; ch < 4; ch++) {
                        acc[0][ch] = __hfma2(wv.h[ch], iv0, acc[0][ch]);
                        acc[1][ch] = __hfma2(wv.h[ch], iv1, acc[1][ch]);
                    }
                }
            }

            __half* ph = p1 + img * 5760 + p * 40 + c0;
            #pragma unroll
            for (int ch = 0; ch < 4; ch++) {
                const float a0 = __low2float(acc[0][ch]);
                const float a1 = __high2float(acc[0][ch]);
                const float c1v = __low2float(acc[1][ch]);
                const float c2v = __high2float(acc[1][ch]);
                const float m = fmaxf(fmaxf(a0, a1), fmaxf(c1v, c2v));
                ph[ch] = __float2half(fmaxf(m + b1_s[c0 + ch], 0.f));
            }
        }
    }

    // ---------------- Phase B: conv2 via fp16 tensor-core GEMM ------------
    // 8 warps = 2 img x 2 m-pairs x 2 n-halves; each warp m32 x n32.
    {
        const int l   = tid & 31;
        const int w   = tid >> 5;
        const int img = w >> 2;
        const int mp  = (w >> 1) & 1;
        const int nh  = w & 1;

        const int lane_r = ((l >> 3) & 1) * 8 + (l & 7);
        const unsigned khalf = ((l >> 4) & 1) * 16;

        unsigned abase[2];
        #pragma unroll
        for (int s = 0; s < 2; s++) {
            const int pos = (mp * 2 + s) * 16 + lane_r;
            abase[s] = (unsigned)(((pos >> 3) * 12 + (pos & 7)) * 80);
        }

        const unsigned aHb = sbase + img * 11520;
        const unsigned BHb = sbase + 23040;

        float acc[2][4][4];
        #pragma unroll
        for (int s = 0; s < 2; s++)
            #pragma unroll
            for (int j = 0; j < 4; j++)
                #pragma unroll
                for (int q = 0; q < 4; q++) acc[s][j][q] = 0.f;

        const char* wt = (const char*)g_w2t;

        for (int ky = 0; ky < 5; ky++) {
            __syncthreads();   // previous slab (or phase-A staging) consumed
            for (int i = tid; i < 1280; i += 256) {
                const int n = i / 20, c = i - n * 20;
                const char* src = wt + n * 1600 + ky * 320 + c * 16;
                char* dst = smem + 23040 + n * 336 + c * 16;
                *(uint4*)dst = *(const uint4*)src;
            }
            __syncthreads();

            const unsigned kyoff = (unsigned)ky * 960;
            for (int kx = 0; kx < 5; kx++) {
                #pragma unroll
                for (int hf = 0; hf < 2; hf++) {
                    const unsigned kb = (unsigned)(kx * 2 + hf) * 32;
                    const unsigned brow = (unsigned)(nh * 32 + l) * 336 + kb;
                    unsigned bh[8];
                    ldsm4(bh[0], bh[1], bh[2], bh[3], BHb + brow);
                    ldsm4(bh[4], bh[5], bh[6], bh[7], BHb + brow + 16);

                    #pragma unroll
                    for (int s = 0; s < 2; s++) {
                        const unsigned ab =
                            abase[s] + kyoff + kx * 80 + khalf + hf * 32;
                        unsigned ah0, ah1, ah2, ah3;
                        ldsm4(ah0, ah1, ah2, ah3, aHb + ab);
                        #pragma unroll
                        for (int j = 0; j < 4; j++)
                            mma_f16(acc[s][j], ah0, ah1, ah2, ah3, bh[j], bh[4 + j]);
                    }
                }
            }
        }

        // epilogue: 2x2 maxpool + bias + relu -> emb1 (fp32 + fp16)
        const long row_img = (long)blockIdx.x * 2 + img;
        #pragma unroll
        for (int s = 0; s < 2; s++) {
            const int mt = mp * 2 + s;
            #pragma unroll
            for (int j = 0; j < 4; j++) {
                float v0 = fmaxf(acc[s][j][0], acc[s][j][2]);
                float v1 = fmaxf(acc[s][j][1], acc[s][j][3]);
                const float u0 = fmaxf(v0, __shfl_down_sync(0xffffffffu, v0, 4));
                const float u1 = fmaxf(v1, __shfl_down_sync(0xffffffffu, v1, 4));
                if (((l >> 2) & 1) == 0) {
                    const int pc = l >> 3;
                    const int p  = mt * 4 + pc;
                    const int nn = nh * 32 + j * 8 + 2 * (l & 3);
                    float2 o;
                    o.x = fmaxf(u0 + b2[nn], 0.f);
                    o.y = fmaxf(u1 + b2[nn + 1], 0.f);
                    const long base = row_img * DIM + p * 64 + nn;
                    *(float2*)&g_emb1[base] = o;
                    __half2 hh;
                    hh.x = __float2half(o.x);
                    hh.y = __float2half(o.y);
                    *(__half2*)&g_emb1f16[base] = hh;
                }
            }
        }
    }
}

// ---------------------------------------------------------------------------
// Tensor-core attention: CTA = 64 rows x 256 units; warps m32 x n64.
// A = emb fp16; B = weights fp16; single-term mma.
// smem: A@0(9216) B@9216(36864) sb@46080 sv@47104 wred@48128
// ---------------------------------------------------------------------------
#define ATT_SMEM 49152

__global__ __launch_bounds__(256, 2) void att_mma_kernel(
    int lvl, const float* __restrict__ b, const float* __restrict__ v,
    const float* __restrict__ vb)
{
    extern __shared__ char sm[];
    const unsigned sb32 = (unsigned)__cvta_generic_to_shared(sm);
    const int tid = threadIdx.x;
    const int row0 = blockIdx.x * 64;

    const __half* ef = lvl == 0 ? g_emb1f16 : (lvl == 1 ? g_emb2f16 : g_emb3f16);
    const __half* wh = g_awt + (size_t)lvl * (NATT * DIM);
    float* s_out = s_buf(lvl);

    float* sbf  = (float*)(sm + 46080);
    float* svf  = (float*)(sm + 47104);
    float* wred = (float*)(sm + 48128);   // [64 rows][4 quarters]
    sbf[tid] = b[tid];
    svf[tid] = v[tid];

    const int l  = tid & 31, w = tid >> 5;
    const int mp = w >> 2;     // m half (rows 0-31 / 32-63)
    const int nq = w & 3;      // n quarter (64 cols)
    const int lane_r = ((l >> 3) & 1) * 8 + (l & 7);
    const unsigned khalf = ((l >> 4) & 1) * 16;

    float acc[2][8][4];
    #pragma unroll
    for (int s = 0; s < 2; s++)
        #pragma unroll
        for (int j = 0; j < 8; j++)
            #pragma unroll
            for (int q = 0; q < 4; q++) acc[s][j][q] = 0.f;

    for (int kc = 0; kc < 16; kc++) {
        __syncthreads();
        const int k0 = kc * 64;
        // stage A: 64 rows x 64 k fp16 (512 uint4)
        for (int i = tid; i < 512; i += 256) {
            const int r = i >> 3, c = i & 7;
            const __half* src = ef + (size_t)(row0 + r) * DIM + k0 + c * 8;
            *(uint4*)(sm + r * 144 + c * 16) = *(const uint4*)src;
        }
        // stage B: 256 n x 64 k (2048 uint4)
        for (int i = tid; i < 2048; i += 256) {
            const int n = i >> 3, c = i & 7;
            const __half* src = wh + (size_t)n * DIM + k0 + c * 8;
            *(uint4*)(sm + 9216 + n * 144 + c * 16) = *(const uint4*)src;
        }
        __syncthreads();

        #pragma unroll
        for (int ks = 0; ks < 4; ks++) {
            unsigned ah[2][4];
            #pragma unroll
            for (int s = 0; s < 2; s++) {
                const unsigned aoff =
                    (unsigned)(mp * 32 + s * 16 + lane_r) * 144 + ks * 32 + khalf;
                ldsm4(ah[s][0], ah[s][1], ah[s][2], ah[s][3], sb32 + aoff);
            }
            #pragma unroll
            for (int g = 0; g < 2; g++) {
                const unsigned boff =
                    (unsigned)(nq * 64 + g * 32 + l) * 144 + ks * 32;
                unsigned b0h[4], b1h[4];
                ldsm4(b0h[0], b0h[1], b0h[2], b0h[3], sb32 + 9216 + boff);
                ldsm4(b1h[0], b1h[1], b1h[2], b1h[3], sb32 + 9216 + boff + 16);
                #pragma unroll
                for (int s = 0; s < 2; s++) {
                    #pragma unroll
                    for (int jj = 0; jj < 4; jj++)
                        mma_f16(acc[s][g * 4 + jj],
                                ah[s][0], ah[s][1], ah[s][2], ah[s][3],
                                b0h[jj], b1h[jj]);
                }
            }
        }
    }

    // epilogue: tanh(h+b)*v, reduce over n -> per-row partials
    #pragma unroll
    for (int s = 0; s < 2; s++) {
        float pvA = 0.f, pvB = 0.f;
        #pragma unroll
        for (int j = 0; j < 8; j++) {
            const int n = nq * 64 + j * 8 + (l & 3) * 2;
            const float b0v = sbf[n], b1v = sbf[n + 1];
            const float v0 = svf[n], v1 = svf[n + 1];
            pvA += tanhf(acc[s][j][0] + b0v) * v0 + tanhf(acc[s][j][1] + b1v) * v1;
            pvB += tanhf(acc[s][j][2] + b0v) * v0 + tanhf(acc[s][j][3] + b1v) * v1;
        }
        pvA += __shfl_xor_sync(0xffffffffu, pvA, 1);
        pvA += __shfl_xor_sync(0xffffffffu, pvA, 2);
        pvB += __shfl_xor_sync(0xffffffffu, pvB, 1);
        pvB += __shfl_xor_sync(0xffffffffu, pvB, 2);
        if ((l & 3) == 0) {
            const int r = mp * 32 + s * 16 + (l >> 2);
            wred[r * 4 + nq]       = pvA;
            wred[(r + 8) * 4 + nq] = pvB;
        }
    }
    __syncthreads();
    if (tid < 64) {
        const float z = wred[tid * 4] + wred[tid * 4 + 1] +
                        wred[tid * 4 + 2] + wred[tid * 4 + 3] + vb[0];
        s_out[row0 + tid] = 1.f / (1.f + expf(-z));
    }
}

// ---------------------------------------------------------------------------
__global__ __launch_bounds__(1024) void stats_kernel(int lvl, int R)
{
    __shared__ float red[1024];
    const float* s = s_buf(lvl);
    const int tid = threadIdx.x;

    float m = -1e30f;
    for (int i = tid; i < R; i += 1024) m = fmaxf(m, s[i]);
    red[tid] = m; __syncthreads();
    for (int off = 512; off; off >>= 1) {
        if (tid < off) red[tid] = fmaxf(red[tid], red[tid + off]);
        __syncthreads();
    }
    const float mx = red[0];
    __syncthreads();

    float sum = 0.f;
    for (int i = tid; i < R; i += 1024) sum += expf(s[i] - mx);
    red[tid] = sum; __syncthreads();
    for (int off = 512; off; off >>= 1) {
        if (tid < off) red[tid] += red[tid + off];
        __syncthreads();
    }
    if (tid == 0) { g_stats[lvl * 2] = mx; g_stats[lvl * 2 + 1] = red[0]; }
}

// ---------------------------------------------------------------------------
// segsum: weighted bag pooling (fp32) + emit fp16 emb for next attention
// ---------------------------------------------------------------------------
__global__ __launch_bounds__(256) void segsum_kernel(int lvl)
{
    __shared__ float ws[16];
    const float* ein  = emb_buf(lvl);
    float*       eout = emb_buf(lvl + 1);
    __half* eoutf = lvl == 0 ? g_emb2f16 : g_emb3f16;
    const float* s    = s_buf(lvl);
    const int bg = blockIdx.x, tid = threadIdx.x;

    if (tid < 16) {
        const float mx = g_stats[lvl * 2];
        const float inv = 1.f / g_stats[lvl * 2 + 1];
        ws[tid] = expf(s[bg * 16 + tid] - mx) * inv;
    }
    __syncthreads();

    const float4* base = (const float4*)(ein + (long)bg * 16 * DIM);
    float4* dst = (float4*)(eout + (long)bg * DIM);
    for (int d = tid; d < DIM / 4; d += 256) {
        float4 a = make_float4(0.f, 0.f, 0.f, 0.f);
        #pragma unroll
        for (int i = 0; i < 16; i++) {
            const float w = ws[i];
            const float4 e = base[i * (DIM / 4) + d];
            a.x += w * e.x; a.y += w * e.y; a.z += w * e.z; a.w += w * e.w;
        }
        dst[d] = a;
        const long eb = (long)bg * DIM + d * 4;
        eoutf[eb + 0] = __float2half(a.x);
        eoutf[eb + 1] = __float2half(a.y);
        eoutf[eb + 2] = __float2half(a.z);
        eoutf[eb + 3] = __float2half(a.w);
    }
}

// ---------------------------------------------------------------------------
__global__ __launch_bounds__(512) void final_kernel(
    const float* __restrict__ clsW, const float* __restrict__ clsb,
    const float* __restrict__ outW, const float* __restrict__ outb,
    float* __restrict__ out)
{
    __shared__ float w3[64];
    __shared__ float outer[DIM];
    __shared__ float red[512];
    const int tid = threadIdx.x;
    const float* s3 = s_buf(2);

    if (tid == 0) {
        float mx = -1e30f;
        for (int i = 0; i < 64; i++) mx = fmaxf(mx, s3[i]);
        float sum = 0.f;
        for (int i = 0; i < 64; i++) { float e = expf(s3[i] - mx); w3[i] = e; sum += e; }
        const float inv = 1.f / sum;
        for (int i = 0; i < 64; i++) w3[i] *= inv;
    }
    __syncthreads();

    for (int d = tid; d < DIM; d += 512) {
        float acc = 0.f;
        #pragma unroll 8
        for (int b2 = 0; b2 < 64; b2++) acc += w3[b2] * g_emb3[b2 * DIM + d];
        outer[d] = acc;
    }
    __syncthreads();

    float acc = 0.f;
    const float* wp = clsW + tid;
    for (int d = 0; d < DIM; d++) acc += outer[d] * wp[d * NCLS];
    red[tid] = (acc + clsb[tid]) * outW[tid];
    __syncthreads();
    for (int off = 256; off; off >>= 1) {
        if (tid < off) red[tid] += red[tid + off];
        __syncthreads();
    }
    if (tid == 0) out[0] = 1.f / (1.f + expf(-(red[0] + outb[0])));
}

// ---------------------------------------------------------------------------
extern "C" void kernel_launch(void* const* d_in, const int* in_sizes, int n_in,
                              void* d_out, int out_size)
{
    const float* x    = (const float*)d_in[0];
    const float* c1w  = (const float*)d_in[1];
    const float* c1b  = (const float*)d_in[2];
    const float* c2w  = (const float*)d_in[3];
    const float* c2b  = (const float*)d_in[4];
    const float* a1W  = (const float*)d_in[5];
    const float* a1b  = (const float*)d_in[6];
    const float* a1v  = (const float*)d_in[7];
    const float* a1vb = (const float*)d_in[8];
    const float* a2W  = (const float*)d_in[9];
    const float* a2b  = (const float*)d_in[10];
    const float* a2v  = (const float*)d_in[11];
    const float* a2vb = (const float*)d_in[12];
    const float* a3W  = (const float*)d_in[13];
    const float* a3b  = (const float*)d_in[14];
    const float* a3v  = (const float*)d_in[15];
    const float* a3vb = (const float*)d_in[16];
    const float* clsW = (const float*)d_in[17];
    const float* clsb = (const float*)d_in[18];
    const float* outW = (const float*)d_in[19];
    const float* outb = (const float*)d_in[20];

    cudaFuncSetAttribute(fused_conv_kernel,
                         cudaFuncAttributeMaxDynamicSharedMemorySize, FC_SMEM);
    cudaFuncSetAttribute(att_mma_kernel,
                         cudaFuncAttributeMaxDynamicSharedMemorySize, ATT_SMEM);

    prep_w2t<<<200, 256>>>(c2w);
    prep_awt_all<<<3072, 256>>>(a1W, a2W, a3W);

    fused_conv_kernel<<<N_INST / 2, 256, FC_SMEM>>>(x, c1w, c1b, c2b);

    att_mma_kernel<<<N_INST / 64, 256, ATT_SMEM>>>(0, a1b, a1v, a1vb);
    stats_kernel<<<1, 1024>>>(0, N_INST);
    segsum_kernel<<<NB1, 256>>>(0);

    att_mma_kernel<<<NB1 / 64, 256, ATT_SMEM>>>(1, a2b, a2v, a2vb);
    stats_kernel<<<1, 1024>>>(1, NB1);
    segsum_kernel<<<NB2, 256>>>(1);

    att_mma_kernel<<<NB2 / 64, 256, ATT_SMEM>>>(2, a3b, a3v, a3vb);
    final_kernel<<<1, 512>>>(clsW, clsb, outW, outb, (float*)d_out);
}

// round 13
// speedup vs baseline: 1.0148x; 1.0148x over previous
#include <cuda_runtime.h>
#include <cuda_fp16.h>
#include <math.h>

#define N_INST 16384
#define NB1    1024
#define NB2    64
#define DIM    1024
#define NATT   256
#define NCLS   512

// ---------------- scratch (device globals; no allocation allowed) ----------
__device__ float g_emb1[N_INST * DIM];   // 64 MB (fp32 for segsum accuracy)
__device__ float g_emb2[NB1 * DIM];
__device__ float g_emb3[NB2 * DIM];
__device__ float g_s[N_INST + NB1 + NB2];
__device__ float g_stats[8];
// conv2 weights, transposed [n=64][k=800], fp16
__device__ __half g_w2t[64 * 800];
// embeddings as fp16 (A-side of attention GEMMs)
__device__ __half g_emb1f16[N_INST * DIM];
__device__ __half g_emb2f16[NB1 * DIM];
__device__ __half g_emb3f16[NB2 * DIM];
// attention weights, transposed [n=256][k=1024], fp16, 3 levels
__device__ __half g_awt[3 * NATT * DIM];

__device__ __forceinline__ float* emb_buf(int lvl) {
    return lvl == 0 ? g_emb1 : (lvl == 1 ? g_emb2 : g_emb3);
}
__device__ __forceinline__ float* s_buf(int lvl) {
    return lvl == 0 ? g_s : (lvl == 1 ? g_s + N_INST : g_s + N_INST + NB1);
}

// ---------------- mma helpers ----------------------------------------------
__device__ __forceinline__ void ldsm4(unsigned& r0, unsigned& r1, unsigned& r2,
                                      unsigned& r3, unsigned a) {
    asm volatile("ldmatrix.sync.aligned.m8n8.x4.shared.b16 {%0,%1,%2,%3}, [%4];"
                 : "=r"(r0), "=r"(r1), "=r"(r2), "=r"(r3) : "r"(a));
}
__device__ __forceinline__ void mma_f16(float* c, unsigned a0, unsigned a1,
                                        unsigned a2, unsigned a3,
                                        unsigned b0, unsigned b1) {
    asm volatile(
        "mma.sync.aligned.m16n8k16.row.col.f32.f16.f16.f32 "
        "{%0,%1,%2,%3},{%4,%5,%6,%7},{%8,%9},{%0,%1,%2,%3};"
        : "+f"(c[0]), "+f"(c[1]), "+f"(c[2]), "+f"(c[3])
        : "r"(a0), "r"(a1), "r"(a2), "r"(a3), "r"(b0), "r"(b1));
}

// ---------------------------------------------------------------------------
// Prep kernels: weight transposes to fp16
// ---------------------------------------------------------------------------
__global__ __launch_bounds__(256) void prep_w2t(const float* __restrict__ w2) {
    const int idx = blockIdx.x * 256 + threadIdx.x;
    if (idx >= 64 * 800) return;
    const int n = idx / 800, k = idx - n * 800;
    g_w2t[idx] = __float2half(w2[k * 64 + n]);
}

__global__ __launch_bounds__(256) void prep_awt_all(
    const float* __restrict__ W0, const float* __restrict__ W1,
    const float* __restrict__ W2)
{
    const int gidx = blockIdx.x * 256 + threadIdx.x;   // 3*262144
    const int set = gidx >> 18;
    const int idx = gidx & 262143;
    const float* W = set == 0 ? W0 : (set == 1 ? W1 : W2);
    const int n = idx >> 10, k = idx & 1023;
    g_awt[set * (NATT * DIM) + idx] = __float2half(W[k * NATT + n]);
}

// ---------------------------------------------------------------------------
// Fused conv kernel: one CTA = 2 images; 2 CTAs/SM.
// Phase A: scalar fp32 conv1 (input patch hoisted to registers) -> p1 fp16.
// Phase B: conv2 implicit GEMM, single-term fp16 mma, DOUBLE-BUFFERED slabs.
// smem: p1[2 img][144*40 fp16] @0 (23040)
//       slab buf0 @23040 (21504) | buf1 @44544 (21504)
//       (Phase A staging reuses 23040..32640)
// ---------------------------------------------------------------------------
#define FC_SMEM 66048

__global__ __launch_bounds__(256, 2) void fused_conv_kernel(
    const float* __restrict__ x,
    const float* __restrict__ w1, const float* __restrict__ b1,
    const float* __restrict__ b2)
{
    extern __shared__ char smem[];
    const unsigned sbase = (unsigned)__cvta_generic_to_shared(smem);
    const int tid = threadIdx.x;

    __half* p1 = (__half*)smem;             // [img][144*40]

    // ---------------- Phase A: conv1 + relu + pool (scalar fp32) ----------
    {
        float* stg  = (float*)(smem + 23040);
        float* w1_s = stg;          // 800
        float* b1_s = stg + 800;    // 32
        float* in_s = stg + 832;    // 2 x 784
        for (int i = tid; i < 800; i += 256) w1_s[i] = w1[i];
        if (tid < 32) b1_s[tid] = b1[tid];
        const float* x0 = x + (size_t)blockIdx.x * 2 * 784;
        for (int i = tid; i < 1568; i += 256) in_s[i] = x0[i];
        __syncthreads();

        for (int t = tid; t < 2304; t += 256) {
            const int img = t >= 1152;
            const int tt  = t - img * 1152;
            const float* in = in_s + img * 784;
            const int c0 = (tt & 7) * 4;
            const int p  = tt >> 3;
            const int pr = p / 12, pc = p % 12;
            const int y0 = pr * 2, xx0 = pc * 2;

            // hoist the 6x6 input patch into registers
            float iv[6][6];
            #pragma unroll
            for (int dy = 0; dy < 6; dy++)
                #pragma unroll
                for (int dx = 0; dx < 6; dx++)
                    iv[dy][dx] = in[(y0 + dy) * 28 + xx0 + dx];

            float acc[4][4];
            #pragma unroll
            for (int j = 0; j < 4; j++)
                #pragma unroll
                for (int ch = 0; ch < 4; ch++) acc[j][ch] = 0.f;

            #pragma unroll
            for (int ky = 0; ky < 5; ky++) {
                #pragma unroll
                for (int kx = 0; kx < 5; kx++) {
                    const float4 wv = *(const float4*)&w1_s[(ky * 5 + kx) * 32 + c0];
                    #pragma unroll
                    for (int j = 0; j < 4; j++) {
                        const float v = iv[(j >> 1) + ky][(j & 1) + kx];
                        acc[j][0] += v * wv.x; acc[j][1] += v * wv.y;
                        acc[j][2] += v * wv.z; acc[j][3] += v * wv.w;
                    }
                }
            }
            __half* ph = p1 + img * 5760 + p * 40 + c0;
            #pragma unroll
            for (int ch = 0; ch < 4; ch++) {
                float m = fmaxf(fmaxf(acc[0][ch], acc[1][ch]),
                                fmaxf(acc[2][ch], acc[3][ch]));
                const float v = fmaxf(m + b1_s[c0 + ch], 0.f);
                ph[ch] = __float2half(v);
            }
        }
    }

    // ---------------- Phase B: conv2 via fp16 tensor-core GEMM ------------
    // 8 warps = 2 img x 2 m-pairs x 2 n-halves; each warp m32 x n32.
    // Double-buffered weight slabs: stage ky+1 while computing ky.
    {
        const int l   = tid & 31;
        const int w   = tid >> 5;
        const int img = w >> 2;
        const int mp  = (w >> 1) & 1;
        const int nh  = w & 1;

        const int lane_r = ((l >> 3) & 1) * 8 + (l & 7);
        const unsigned khalf = ((l >> 4) & 1) * 16;

        unsigned abase[2];
        #pragma unroll
        for (int s = 0; s < 2; s++) {
            const int pos = (mp * 2 + s) * 16 + lane_r;
            abase[s] = (unsigned)(((pos >> 3) * 12 + (pos & 7)) * 80);
        }

        const unsigned aHb = sbase + img * 11520;

        float acc[2][4][4];
        #pragma unroll
        for (int s = 0; s < 2; s++)
            #pragma unroll
            for (int j = 0; j < 4; j++)
                #pragma unroll
                for (int q = 0; q < 4; q++) acc[s][j][q] = 0.f;

        const char* wt = (const char*)g_w2t;

        // stage slab 0 (Phase A staging area is dead after this barrier)
        __syncthreads();
        for (int i = tid; i < 1280; i += 256) {
            const int n = i / 20, c = i - n * 20;
            *(uint4*)(smem + 23040 + n * 336 + c * 16) =
                *(const uint4*)(wt + n * 1600 + c * 16);
        }
        __syncthreads();

        for (int ky = 0; ky < 5; ky++) {
            // prefetch slab ky+1 into the other buffer (no barrier needed:
            // it writes the buffer nobody reads this iteration)
            if (ky < 4) {
                const int buf = (ky + 1) & 1;
                for (int i = tid; i < 1280; i += 256) {
                    const int n = i / 20, c = i - n * 20;
                    *(uint4*)(smem + 23040 + buf * 21504 + n * 336 + c * 16) =
                        *(const uint4*)(wt + n * 1600 + (ky + 1) * 320 + c * 16);
                }
            }

            const unsigned BHb = sbase + 23040 + (unsigned)(ky & 1) * 21504;
            const unsigned kyoff = (unsigned)ky * 960;
            for (int kx = 0; kx < 5; kx++) {
                #pragma unroll
                for (int hf = 0; hf < 2; hf++) {
                    const unsigned kb = (unsigned)(kx * 2 + hf) * 32;
                    const unsigned brow = (unsigned)(nh * 32 + l) * 336 + kb;
                    unsigned bh[8];
                    ldsm4(bh[0], bh[1], bh[2], bh[3], BHb + brow);
                    ldsm4(bh[4], bh[5], bh[6], bh[7], BHb + brow + 16);

                    #pragma unroll
                    for (int s = 0; s < 2; s++) {
                        const unsigned ab =
                            abase[s] + kyoff + kx * 80 + khalf + hf * 32;
                        unsigned ah0, ah1, ah2, ah3;
                        ldsm4(ah0, ah1, ah2, ah3, aHb + ab);
                        #pragma unroll
                        for (int j = 0; j < 4; j++)
                            mma_f16(acc[s][j], ah0, ah1, ah2, ah3, bh[j], bh[4 + j]);
                    }
                }
            }
            __syncthreads();   // staging of ky+1 complete; compute of ky done
        }

        // epilogue: 2x2 maxpool + bias + relu -> emb1 (fp32 + fp16)
        const long row_img = (long)blockIdx.x * 2 + img;
        #pragma unroll
        for (int s = 0; s < 2; s++) {
            const int mt = mp * 2 + s;
            #pragma unroll
            for (int j = 0; j < 4; j++) {
                float v0 = fmaxf(acc[s][j][0], acc[s][j][2]);
                float v1 = fmaxf(acc[s][j][1], acc[s][j][3]);
                const float u0 = fmaxf(v0, __shfl_down_sync(0xffffffffu, v0, 4));
                const float u1 = fmaxf(v1, __shfl_down_sync(0xffffffffu, v1, 4));
                if (((l >> 2) & 1) == 0) {
                    const int pc = l >> 3;
                    const int p  = mt * 4 + pc;
                    const int nn = nh * 32 + j * 8 + 2 * (l & 3);
                    float2 o;
                    o.x = fmaxf(u0 + b2[nn], 0.f);
                    o.y = fmaxf(u1 + b2[nn + 1], 0.f);
                    const long base = row_img * DIM + p * 64 + nn;
                    *(float2*)&g_emb1[base] = o;
                    __half2 hh;
                    hh.x = __float2half(o.x);
                    hh.y = __float2half(o.y);
                    *(__half2*)&g_emb1f16[base] = hh;
                }
            }
        }
    }
}

// ---------------------------------------------------------------------------
// Tensor-core attention: CTA = 64 rows x 256 units; warps m32 x n64.
// A = emb fp16; B = weights fp16; single-term mma.
// smem: A@0(9216) B@9216(36864) sb@46080 sv@47104 wred@48128
// ---------------------------------------------------------------------------
#define ATT_SMEM 49152

__global__ __launch_bounds__(256, 2) void att_mma_kernel(
    int lvl, const float* __restrict__ b, const float* __restrict__ v,
    const float* __restrict__ vb)
{
    extern __shared__ char sm[];
    const unsigned sb32 = (unsigned)__cvta_generic_to_shared(sm);
    const int tid = threadIdx.x;
    const int row0 = blockIdx.x * 64;

    const __half* ef = lvl == 0 ? g_emb1f16 : (lvl == 1 ? g_emb2f16 : g_emb3f16);
    const __half* wh = g_awt + (size_t)lvl * (NATT * DIM);
    float* s_out = s_buf(lvl);

    float* sbf  = (float*)(sm + 46080);
    float* svf  = (float*)(sm + 47104);
    float* wred = (float*)(sm + 48128);   // [64 rows][4 quarters]
    sbf[tid] = b[tid];
    svf[tid] = v[tid];

    const int l  = tid & 31, w = tid >> 5;
    const int mp = w >> 2;     // m half (rows 0-31 / 32-63)
    const int nq = w & 3;      // n quarter (64 cols)
    const int lane_r = ((l >> 3) & 1) * 8 + (l & 7);
    const unsigned khalf = ((l >> 4) & 1) * 16;

    float acc[2][8][4];
    #pragma unroll
    for (int s = 0; s < 2; s++)
        #pragma unroll
        for (int j = 0; j < 8; j++)
            #pragma unroll
            for (int q = 0; q < 4; q++) acc[s][j][q] = 0.f;

    for (int kc = 0; kc < 16; kc++) {
        __syncthreads();
        const int k0 = kc * 64;
        // stage A: 64 rows x 64 k fp16 (512 uint4)
        for (int i = tid; i < 512; i += 256) {
            const int r = i >> 3, c = i & 7;
            const __half* src = ef + (size_t)(row0 + r) * DIM + k0 + c * 8;
            *(uint4*)(sm + r * 144 + c * 16) = *(const uint4*)src;
        }
        // stage B: 256 n x 64 k (2048 uint4)
        for (int i = tid; i < 2048; i += 256) {
            const int n = i >> 3, c = i & 7;
            const __half* src = wh + (size_t)n * DIM + k0 + c * 8;
            *(uint4*)(sm + 9216 + n * 144 + c * 16) = *(const uint4*)src;
        }
        __syncthreads();

        #pragma unroll
        for (int ks = 0; ks < 4; ks++) {
            unsigned ah[2][4];
            #pragma unroll
            for (int s = 0; s < 2; s++) {
                const unsigned aoff =
                    (unsigned)(mp * 32 + s * 16 + lane_r) * 144 + ks * 32 + khalf;
                ldsm4(ah[s][0], ah[s][1], ah[s][2], ah[s][3], sb32 + aoff);
            }
            #pragma unroll
            for (int g = 0; g < 2; g++) {
                const unsigned boff =
                    (unsigned)(nq * 64 + g * 32 + l) * 144 + ks * 32;
                unsigned b0h[4], b1h[4];
                ldsm4(b0h[0], b0h[1], b0h[2], b0h[3], sb32 + 9216 + boff);
                ldsm4(b1h[0], b1h[1], b1h[2], b1h[3], sb32 + 9216 + boff + 16);
                #pragma unroll
                for (int s = 0; s < 2; s++) {
                    #pragma unroll
                    for (int jj = 0; jj < 4; jj++)
                        mma_f16(acc[s][g * 4 + jj],
                                ah[s][0], ah[s][1], ah[s][2], ah[s][3],
                                b0h[jj], b1h[jj]);
                }
            }
        }
    }

    // epilogue: tanh(h+b)*v, reduce over n -> per-row partials
    #pragma unroll
    for (int s = 0; s < 2; s++) {
        float pvA = 0.f, pvB = 0.f;
        #pragma unroll
        for (int j = 0; j < 8; j++) {
            const int n = nq * 64 + j * 8 + (l & 3) * 2;
            const float b0v = sbf[n], b1v = sbf[n + 1];
            const float v0 = svf[n], v1 = svf[n + 1];
            pvA += tanhf(acc[s][j][0] + b0v) * v0 + tanhf(acc[s][j][1] + b1v) * v1;
            pvB += tanhf(acc[s][j][2] + b0v) * v0 + tanhf(acc[s][j][3] + b1v) * v1;
        }
        pvA += __shfl_xor_sync(0xffffffffu, pvA, 1);
        pvA += __shfl_xor_sync(0xffffffffu, pvA, 2);
        pvB += __shfl_xor_sync(0xffffffffu, pvB, 1);
        pvB += __shfl_xor_sync(0xffffffffu, pvB, 2);
        if ((l & 3) == 0) {
            const int r = mp * 32 + s * 16 + (l >> 2);
            wred[r * 4 + nq]       = pvA;
            wred[(r + 8) * 4 + nq] = pvB;
        }
    }
    __syncthreads();
    if (tid < 64) {
        const float z = wred[tid * 4] + wred[tid * 4 + 1] +
                        wred[tid * 4 + 2] + wred[tid * 4 + 3] + vb[0];
        s_out[row0 + tid] = 1.f / (1.f + expf(-z));
    }
}

// ---------------------------------------------------------------------------
__global__ __launch_bounds__(1024) void stats_kernel(int lvl, int R)
{
    __shared__ float red[1024];
    const float* s = s_buf(lvl);
    const int tid = threadIdx.x;

    float m = -1e30f;
    for (int i = tid; i < R; i += 1024) m = fmaxf(m, s[i]);
    red[tid] = m; __syncthreads();
    for (int off = 512; off; off >>= 1) {
        if (tid < off) red[tid] = fmaxf(red[tid], red[tid + off]);
        __syncthreads();
    }
    const float mx = red[0];
    __syncthreads();

    float sum = 0.f;
    for (int i = tid; i < R; i += 1024) sum += expf(s[i] - mx);
    red[tid] = sum; __syncthreads();
    for (int off = 512; off; off >>= 1) {
        if (tid < off) red[tid] += red[tid + off];
        __syncthreads();
    }
    if (tid == 0) { g_stats[lvl * 2] = mx; g_stats[lvl * 2 + 1] = red[0]; }
}

// ---------------------------------------------------------------------------
// segsum: weighted bag pooling (fp32) + emit fp16 emb for next attention
// ---------------------------------------------------------------------------
__global__ __launch_bounds__(256) void segsum_kernel(int lvl)
{
    __shared__ float ws[16];
    const float* ein  = emb_buf(lvl);
    float*       eout = emb_buf(lvl + 1);
    __half* eoutf = lvl == 0 ? g_emb2f16 : g_emb3f16;
    const float* s    = s_buf(lvl);
    const int bg = blockIdx.x, tid = threadIdx.x;

    if (tid < 16) {
        const float mx = g_stats[lvl * 2];
        const float inv = 1.f / g_stats[lvl * 2 + 1];
        ws[tid] = expf(s[bg * 16 + tid] - mx) * inv;
    }
    __syncthreads();

    const float4* base = (const float4*)(ein + (long)bg * 16 * DIM);
    float4* dst = (float4*)(eout + (long)bg * DIM);
    for (int d = tid; d < DIM / 4; d += 256) {
        float4 a = make_float4(0.f, 0.f, 0.f, 0.f);
        #pragma unroll
        for (int i = 0; i < 16; i++) {
            const float w = ws[i];
            const float4 e = base[i * (DIM / 4) + d];
            a.x += w * e.x; a.y += w * e.y; a.z += w * e.z; a.w += w * e.w;
        }
        dst[d] = a;
        const long eb = (long)bg * DIM + d * 4;
        eoutf[eb + 0] = __float2half(a.x);
        eoutf[eb + 1] = __float2half(a.y);
        eoutf[eb + 2] = __float2half(a.z);
        eoutf[eb + 3] = __float2half(a.w);
    }
}

// ---------------------------------------------------------------------------
__global__ __launch_bounds__(512) void final_kernel(
    const float* __restrict__ clsW, const float* __restrict__ clsb,
    const float* __restrict__ outW, const float* __restrict__ outb,
    float* __restrict__ out)
{
    __shared__ float w3[64];
    __shared__ float outer[DIM];
    __shared__ float red[512];
    const int tid = threadIdx.x;
    const float* s3 = s_buf(2);

    if (tid == 0) {
        float mx = -1e30f;
        for (int i = 0; i < 64; i++) mx = fmaxf(mx, s3[i]);
        float sum = 0.f;
        for (int i = 0; i < 64; i++) { float e = expf(s3[i] - mx); w3[i] = e; sum += e; }
        const float inv = 1.f / sum;
        for (int i = 0; i < 64; i++) w3[i] *= inv;
    }
    __syncthreads();

    for (int d = tid; d < DIM; d += 512) {
        float acc = 0.f;
        #pragma unroll 8
        for (int b2 = 0; b2 < 64; b2++) acc += w3[b2] * g_emb3[b2 * DIM + d];
        outer[d] = acc;
    }
    __syncthreads();

    float acc = 0.f;
    const float* wp = clsW + tid;
    for (int d = 0; d < DIM; d++) acc += outer[d] * wp[d * NCLS];
    red[tid] = (acc + clsb[tid]) * outW[tid];
    __syncthreads();
    for (int off = 256; off; off >>= 1) {
        if (tid < off) red[tid] += red[tid + off];
        __syncthreads();
    }
    if (tid == 0) out[0] = 1.f / (1.f + expf(-(red[0] + outb[0])));
}

// ---------------------------------------------------------------------------
extern "C" void kernel_launch(void* const* d_in, const int* in_sizes, int n_in,
                              void* d_out, int out_size)
{
    const float* x    = (const float*)d_in[0];
    const float* c1w  = (const float*)d_in[1];
    const float* c1b  = (const float*)d_in[2];
    const float* c2w  = (const float*)d_in[3];
    const float* c2b  = (const float*)d_in[4];
    const float* a1W  = (const float*)d_in[5];
    const float* a1b  = (const float*)d_in[6];
    const float* a1v  = (const float*)d_in[7];
    const float* a1vb = (const float*)d_in[8];
    const float* a2W  = (const float*)d_in[9];
    const float* a2b  = (const float*)d_in[10];
    const float* a2v  = (const float*)d_in[11];
    const float* a2vb = (const float*)d_in[12];
    const float* a3W  = (const float*)d_in[13];
    const float* a3b  = (const float*)d_in[14];
    const float* a3v  = (const float*)d_in[15];
    const float* a3vb = (const float*)d_in[16];
    const float* clsW = (const float*)d_in[17];
    const float* clsb = (const float*)d_in[18];
    const float* outW = (const float*)d_in[19];
    const float* outb = (const float*)d_in[20];

    cudaFuncSetAttribute(fused_conv_kernel,
                         cudaFuncAttributeMaxDynamicSharedMemorySize, FC_SMEM);
    cudaFuncSetAttribute(att_mma_kernel,
                         cudaFuncAttributeMaxDynamicSharedMemorySize, ATT_SMEM);

    prep_w2t<<<200, 256>>>(c2w);
    prep_awt_all<<<3072, 256>>>(a1W, a2W, a3W);

    fused_conv_kernel<<<N_INST / 2, 256, FC_SMEM>>>(x, c1w, c1b, c2b);

    att_mma_kernel<<<N_INST / 64, 256, ATT_SMEM>>>(0, a1b, a1v, a1vb);
    stats_kernel<<<1, 1024>>>(0, N_INST);
    segsum_kernel<<<NB1, 256>>>(0);

    att_mma_kernel<<<NB1 / 64, 256, ATT_SMEM>>>(1, a2b, a2v, a2vb);
    stats_kernel<<<1, 1024>>>(1, NB1);
    segsum_kernel<<<NB2, 256>>>(1);

    att_mma_kernel<<<NB2 / 64, 256, ATT_SMEM>>>(2, a3b, a3v, a3vb);
    final_kernel<<<1, 512>>>(clsW, clsb, outW, outb, (float*)d_out);
}

// round 14
// speedup vs baseline: 1.1781x; 1.1609x over previous
#include <cuda_runtime.h>
#include <cuda_fp16.h>
#include <math.h>

#define N_INST 16384
#define NB1    1024
#define NB2    64
#define DIM    1024
#define NATT   256
#define NCLS   512

// ---------------- scratch (device globals; no allocation allowed) ----------
__device__ float g_emb1[N_INST * DIM];   // 64 MB (fp32 for segsum accuracy)
__device__ float g_emb2[NB1 * DIM];
__device__ float g_emb3[NB2 * DIM];
__device__ float g_s[N_INST + NB1 + NB2];
__device__ float g_stats[8];
// conv2 weights, transposed [n=64][k=800], fp16
__device__ __half g_w2t[64 * 800];
// embeddings as fp16 (A-side of attention GEMMs)
__device__ __half g_emb1f16[N_INST * DIM];
__device__ __half g_emb2f16[NB1 * DIM];
__device__ __half g_emb3f16[NB2 * DIM];
// attention weights, transposed [n=256][k=1024], fp16, 3 levels
__device__ __half g_awt[3 * NATT * DIM];

__device__ __forceinline__ float* emb_buf(int lvl) {
    return lvl == 0 ? g_emb1 : (lvl == 1 ? g_emb2 : g_emb3);
}
__device__ __forceinline__ float* s_buf(int lvl) {
    return lvl == 0 ? g_s : (lvl == 1 ? g_s + N_INST : g_s + N_INST + NB1);
}

// ---------------- mma helpers ----------------------------------------------
__device__ __forceinline__ void ldsm4(unsigned& r0, unsigned& r1, unsigned& r2,
                                      unsigned& r3, unsigned a) {
    asm volatile("ldmatrix.sync.aligned.m8n8.x4.shared.b16 {%0,%1,%2,%3}, [%4];"
                 : "=r"(r0), "=r"(r1), "=r"(r2), "=r"(r3) : "r"(a));
}
__device__ __forceinline__ void mma_f16(float* c, unsigned a0, unsigned a1,
                                        unsigned a2, unsigned a3,
                                        unsigned b0, unsigned b1) {
    asm volatile(
        "mma.sync.aligned.m16n8k16.row.col.f32.f16.f16.f32 "
        "{%0,%1,%2,%3},{%4,%5,%6,%7},{%8,%9},{%0,%1,%2,%3};"
        : "+f"(c[0]), "+f"(c[1]), "+f"(c[2]), "+f"(c[3])
        : "r"(a0), "r"(a1), "r"(a2), "r"(a3), "r"(b0), "r"(b1));
}

// ---------------------------------------------------------------------------
// Prep kernels: weight transposes to fp16
// ---------------------------------------------------------------------------
__global__ __launch_bounds__(256) void prep_w2t(const float* __restrict__ w2) {
    const int idx = blockIdx.x * 256 + threadIdx.x;
    if (idx >= 64 * 800) return;
    const int n = idx / 800, k = idx - n * 800;
    g_w2t[idx] = __float2half(w2[k * 64 + n]);
}

__global__ __launch_bounds__(256) void prep_awt_all(
    const float* __restrict__ W0, const float* __restrict__ W1,
    const float* __restrict__ W2)
{
    const int gidx = blockIdx.x * 256 + threadIdx.x;   // 3*262144
    const int set = gidx >> 18;
    const int idx = gidx & 262143;
    const float* W = set == 0 ? W0 : (set == 1 ? W1 : W2);
    const int n = idx >> 10, k = idx & 1023;
    g_awt[set * (NATT * DIM) + idx] = __float2half(W[k * NATT + n]);
}

// ---------------------------------------------------------------------------
// Fused conv kernel: one CTA = 2 images; 2 CTAs/SM.
// Phase A: conv1 on TENSOR CORES. im2col A (row = pooled_pos*4 + member,
//   k = 25 taps padded to 32) built in 3 chunks of 192 rows per image with a
//   cheap per-row copy loop; C[192,32] = A x w1B via m16n8k16; 2x2 maxpool
//   collapses inside the C fragment (shfl_xor 4,8); writes p1 fp16 planes.
// Phase B: conv2 implicit GEMM, single-term fp16 mma (R11, unchanged).
// smem map (bytes):
//   0     p1[2 img][144*40 fp16]                 23040
//   23040 Abuf[2 img][192 rows * 40 fp16]        30720  (Phase B slab reuses)
//   53760 in16[2 img][784 fp16]                   3136
//   56896 w1B [32 n][40 fp16] (taps>=25 zero)     2560
//   59456 b1_s[32 f]                               128
// ---------------------------------------------------------------------------
#define FC_SMEM 59584

__global__ __launch_bounds__(256, 2) void fused_conv_kernel(
    const float* __restrict__ x,
    const float* __restrict__ w1, const float* __restrict__ b1,
    const float* __restrict__ b2)
{
    extern __shared__ char smem[];
    const unsigned sbase = (unsigned)__cvta_generic_to_shared(smem);
    const int tid = threadIdx.x;
    const int l = tid & 31, w = tid >> 5;
    const int lane_r = ((l >> 3) & 1) * 8 + (l & 7);
    const unsigned khalf = ((l >> 4) & 1) * 16;

    __half* p1   = (__half*)smem;              // [img][144*40]
    __half* Abuf = (__half*)(smem + 23040);    // [img][192*40]
    __half* in16 = (__half*)(smem + 53760);    // [img][784]
    __half* w1B  = (__half*)(smem + 56896);    // [32][40]
    float*  b1_s = (float*)(smem + 59456);

    // ---------------- Phase A: conv1 via tensor cores ---------------------
    {
        // stage input (fp16), w1 B-tile (transposed, k-pad zeroed), bias,
        // and zero the A buffer (pad cols stay zero forever)
        const float* x0 = x + (size_t)blockIdx.x * 2 * 784;
        for (int i = tid; i < 1568; i += 256) in16[i] = __float2half(x0[i]);
        for (int i = tid; i < 1280; i += 256) {          // 32 rows x 40 cols
            const int n = i / 40, c = i - n * 40;
            const float v = (c < 25) ? w1[c * 32 + n] : 0.f;
            w1B[n * 40 + c] = __float2half(v);
        }
        if (tid < 32) b1_s[tid] = b1[tid];
        {
            const uint4 z4 = make_uint4(0u, 0u, 0u, 0u);
            for (int i = tid; i < 1920; i += 256)
                *(uint4*)(smem + 23040 + i * 16) = z4;
        }
        __syncthreads();

        // per-warp B fragments (same w1 for both images), held in registers
        unsigned wb[16];
        {
            const unsigned bB = sbase + 56896 + (unsigned)l * 80;
            ldsm4(wb[0],  wb[1],  wb[2],  wb[3],  bB);
            ldsm4(wb[4],  wb[5],  wb[6],  wb[7],  bB + 16);
            ldsm4(wb[8],  wb[9],  wb[10], wb[11], bB + 32);
            ldsm4(wb[12], wb[13], wb[14], wb[15], bB + 48);
        }

        const int wimg = w >> 2;     // image this warp computes
        const int wq   = w & 3;      // tile group within chunk

        for (int chunk = 0; chunk < 3; chunk++) {
            // ---- build A chunk: 192 rows x 25 taps, both images ----
            for (int slot = tid; slot < 384; slot += 256) {
                const int bimg = slot >= 192;
                const int rl   = slot - bimg * 192;
                const int p    = chunk * 48 + (rl >> 2);
                const int mem  = rl & 3;
                const int pr = p / 12, pc = p - pr * 12;
                const __half* src =
                    in16 + bimg * 784 +
                    (2 * pr + (mem >> 1)) * 28 + 2 * pc + (mem & 1);
                __half* dst = Abuf + bimg * 7680 + rl * 40;
                #pragma unroll
                for (int ky = 0; ky < 5; ky++)
                    #pragma unroll
                    for (int kx = 0; kx < 5; kx++)
                        dst[ky * 5 + kx] = src[ky * 28 + kx];
            }
            __syncthreads();

            // ---- mma + pooled epilogue: 12 m-tiles, 3 per warp ----
            const unsigned AbB = sbase + 23040 + (unsigned)wimg * 15360;
            #pragma unroll
            for (int ti = 0; ti < 3; ti++) {
                const int tile = wq + ti * 4;
                const unsigned ar = AbB + (unsigned)(tile * 16 + lane_r) * 80;
                unsigned a0, a1, a2, a3, a4, a5, a6, a7;
                ldsm4(a0, a1, a2, a3, ar + khalf);        // k0-15
                ldsm4(a4, a5, a6, a7, ar + 32 + khalf);   // k16-31

                float acc[4][4];
                #pragma unroll
                for (int j = 0; j < 4; j++)
                    #pragma unroll
                    for (int q = 0; q < 4; q++) acc[j][q] = 0.f;
                #pragma unroll
                for (int j = 0; j < 4; j++) {
                    mma_f16(acc[j], a0, a1, a2, a3, wb[j], wb[4 + j]);
                    mma_f16(acc[j], a4, a5, a6, a7, wb[8 + j], wb[12 + j]);
                }

                // pool over the 4 member-rows inside the fragment
                const int pbase = chunk * 48 + tile * 4;
                #pragma unroll
                for (int j = 0; j < 4; j++) {
                    float m0 = acc[j][0], m1 = acc[j][1];
                    float m2 = acc[j][2], m3 = acc[j][3];
                    m0 = fmaxf(m0, __shfl_xor_sync(0xffffffffu, m0, 4));
                    m0 = fmaxf(m0, __shfl_xor_sync(0xffffffffu, m0, 8));
                    m1 = fmaxf(m1, __shfl_xor_sync(0xffffffffu, m1, 4));
                    m1 = fmaxf(m1, __shfl_xor_sync(0xffffffffu, m1, 8));
                    m2 = fmaxf(m2, __shfl_xor_sync(0xffffffffu, m2, 4));
                    m2 = fmaxf(m2, __shfl_xor_sync(0xffffffffu, m2, 8));
                    m3 = fmaxf(m3, __shfl_xor_sync(0xffffffffu, m3, 4));
                    m3 = fmaxf(m3, __shfl_xor_sync(0xffffffffu, m3, 8));
                    if ((l & 12) == 0) {
                        const int q  = l >> 4;               // 0/1
                        const int ch = j * 8 + 2 * (l & 3);
                        const float bA = b1_s[ch], bB2 = b1_s[ch + 1];
                        __half2 o1, o2;
                        o1.x = __float2half(fmaxf(m0 + bA, 0.f));
                        o1.y = __float2half(fmaxf(m1 + bB2, 0.f));
                        o2.x = __float2half(fmaxf(m2 + bA, 0.f));
                        o2.y = __float2half(fmaxf(m3 + bB2, 0.f));
                        __half* pp = p1 + wimg * 5760;
                        *(__half2*)&pp[(pbase + q) * 40 + ch]     = o1;
                        *(__half2*)&pp[(pbase + 2 + q) * 40 + ch] = o2;
                    }
                }
            }
            __syncthreads();   // mma done before next build / Phase B staging
        }
    }

    // ---------------- Phase B: conv2 via fp16 tensor-core GEMM ------------
    // 8 warps = 2 img x 2 m-pairs x 2 n-halves; each warp m32 x n32. (R11)
    {
        const int img = w >> 2;
        const int mp  = (w >> 1) & 1;
        const int nh  = w & 1;

        unsigned abase[2];
        #pragma unroll
        for (int s = 0; s < 2; s++) {
            const int pos = (mp * 2 + s) * 16 + lane_r;
            abase[s] = (unsigned)(((pos >> 3) * 12 + (pos & 7)) * 80);
        }

        const unsigned aHb = sbase + img * 11520;
        const unsigned BHb = sbase + 23040;

        float acc[2][4][4];
        #pragma unroll
        for (int s = 0; s < 2; s++)
            #pragma unroll
            for (int j = 0; j < 4; j++)
                #pragma unroll
                for (int q = 0; q < 4; q++) acc[s][j][q] = 0.f;

        const char* wt = (const char*)g_w2t;

        for (int ky = 0; ky < 5; ky++) {
            __syncthreads();   // previous slab (or phase-A Abuf) consumed
            for (int i = tid; i < 1280; i += 256) {
                const int n = i / 20, c = i - n * 20;
                const char* src = wt + n * 1600 + ky * 320 + c * 16;
                char* dst = smem + 23040 + n * 336 + c * 16;
                *(uint4*)dst = *(const uint4*)src;
            }
            __syncthreads();

            const unsigned kyoff = (unsigned)ky * 960;
            for (int kx = 0; kx < 5; kx++) {
                #pragma unroll
                for (int hf = 0; hf < 2; hf++) {
                    const unsigned kb = (unsigned)(kx * 2 + hf) * 32;
                    const unsigned brow = (unsigned)(nh * 32 + l) * 336 + kb;
                    unsigned bh[8];
                    ldsm4(bh[0], bh[1], bh[2], bh[3], BHb + brow);
                    ldsm4(bh[4], bh[5], bh[6], bh[7], BHb + brow + 16);

                    #pragma unroll
                    for (int s = 0; s < 2; s++) {
                        const unsigned ab =
                            abase[s] + kyoff + kx * 80 + khalf + hf * 32;
                        unsigned ah0, ah1, ah2, ah3;
                        ldsm4(ah0, ah1, ah2, ah3, aHb + ab);
                        #pragma unroll
                        for (int j = 0; j < 4; j++)
                            mma_f16(acc[s][j], ah0, ah1, ah2, ah3, bh[j], bh[4 + j]);
                    }
                }
            }
        }

        // epilogue: 2x2 maxpool + bias + relu -> emb1 (fp32 + fp16)
        const long row_img = (long)blockIdx.x * 2 + img;
        #pragma unroll
        for (int s = 0; s < 2; s++) {
            const int mt = mp * 2 + s;
            #pragma unroll
            for (int j = 0; j < 4; j++) {
                float v0 = fmaxf(acc[s][j][0], acc[s][j][2]);
                float v1 = fmaxf(acc[s][j][1], acc[s][j][3]);
                const float u0 = fmaxf(v0, __shfl_down_sync(0xffffffffu, v0, 4));
                const float u1 = fmaxf(v1, __shfl_down_sync(0xffffffffu, v1, 4));
                if (((l >> 2) & 1) == 0) {
                    const int pc = l >> 3;
                    const int p  = mt * 4 + pc;
                    const int nn = nh * 32 + j * 8 + 2 * (l & 3);
                    float2 o;
                    o.x = fmaxf(u0 + b2[nn], 0.f);
                    o.y = fmaxf(u1 + b2[nn + 1], 0.f);
                    const long base = row_img * DIM + p * 64 + nn;
                    *(float2*)&g_emb1[base] = o;
                    __half2 hh;
                    hh.x = __float2half(o.x);
                    hh.y = __float2half(o.y);
                    *(__half2*)&g_emb1f16[base] = hh;
                }
            }
        }
    }
}

// ---------------------------------------------------------------------------
// Tensor-core attention: CTA = 64 rows x 256 units; warps m32 x n64.
// A = emb fp16; B = weights fp16; single-term mma. (R11, unchanged)
// smem: A@0(9216) B@9216(36864) sb@46080 sv@47104 wred@48128
// ---------------------------------------------------------------------------
#define ATT_SMEM 49152

__global__ __launch_bounds__(256, 2) void att_mma_kernel(
    int lvl, const float* __restrict__ b, const float* __restrict__ v,
    const float* __restrict__ vb)
{
    extern __shared__ char sm[];
    const unsigned sb32 = (unsigned)__cvta_generic_to_shared(sm);
    const int tid = threadIdx.x;
    const int row0 = blockIdx.x * 64;

    const __half* ef = lvl == 0 ? g_emb1f16 : (lvl == 1 ? g_emb2f16 : g_emb3f16);
    const __half* wh = g_awt + (size_t)lvl * (NATT * DIM);
    float* s_out = s_buf(lvl);

    float* sbf  = (float*)(sm + 46080);
    float* svf  = (float*)(sm + 47104);
    float* wred = (float*)(sm + 48128);   // [64 rows][4 quarters]
    sbf[tid] = b[tid];
    svf[tid] = v[tid];

    const int l  = tid & 31, w = tid >> 5;
    const int mp = w >> 2;     // m half (rows 0-31 / 32-63)
    const int nq = w & 3;      // n quarter (64 cols)
    const int lane_r = ((l >> 3) & 1) * 8 + (l & 7);
    const unsigned khalf = ((l >> 4) & 1) * 16;

    float acc[2][8][4];
    #pragma unroll
    for (int s = 0; s < 2; s++)
        #pragma unroll
        for (int j = 0; j < 8; j++)
            #pragma unroll
            for (int q = 0; q < 4; q++) acc[s][j][q] = 0.f;

    for (int kc = 0; kc < 16; kc++) {
        __syncthreads();
        const int k0 = kc * 64;
        // stage A: 64 rows x 64 k fp16 (512 uint4)
        for (int i = tid; i < 512; i += 256) {
            const int r = i >> 3, c = i & 7;
            const __half* src = ef + (size_t)(row0 + r) * DIM + k0 + c * 8;
            *(uint4*)(sm + r * 144 + c * 16) = *(const uint4*)src;
        }
        // stage B: 256 n x 64 k (2048 uint4)
        for (int i = tid; i < 2048; i += 256) {
            const int n = i >> 3, c = i & 7;
            const __half* src = wh + (size_t)n * DIM + k0 + c * 8;
            *(uint4*)(sm + 9216 + n * 144 + c * 16) = *(const uint4*)src;
        }
        __syncthreads();

        #pragma unroll
        for (int ks = 0; ks < 4; ks++) {
            unsigned ah[2][4];
            #pragma unroll
            for (int s = 0; s < 2; s++) {
                const unsigned aoff =
                    (unsigned)(mp * 32 + s * 16 + lane_r) * 144 + ks * 32 + khalf;
                ldsm4(ah[s][0], ah[s][1], ah[s][2], ah[s][3], sb32 + aoff);
            }
            #pragma unroll
            for (int g = 0; g < 2; g++) {
                const unsigned boff =
                    (unsigned)(nq * 64 + g * 32 + l) * 144 + ks * 32;
                unsigned b0h[4], b1h[4];
                ldsm4(b0h[0], b0h[1], b0h[2], b0h[3], sb32 + 9216 + boff);
                ldsm4(b1h[0], b1h[1], b1h[2], b1h[3], sb32 + 9216 + boff + 16);
                #pragma unroll
                for (int s = 0; s < 2; s++) {
                    #pragma unroll
                    for (int jj = 0; jj < 4; jj++)
                        mma_f16(acc[s][g * 4 + jj],
                                ah[s][0], ah[s][1], ah[s][2], ah[s][3],
                                b0h[jj], b1h[jj]);
                }
            }
        }
    }

    // epilogue: tanh(h+b)*v, reduce over n -> per-row partials
    #pragma unroll
    for (int s = 0; s < 2; s++) {
        float pvA = 0.f, pvB = 0.f;
        #pragma unroll
        for (int j = 0; j < 8; j++) {
            const int n = nq * 64 + j * 8 + (l & 3) * 2;
            const float b0v = sbf[n], b1v = sbf[n + 1];
            const float v0 = svf[n], v1 = svf[n + 1];
            pvA += tanhf(acc[s][j][0] + b0v) * v0 + tanhf(acc[s][j][1] + b1v) * v1;
            pvB += tanhf(acc[s][j][2] + b0v) * v0 + tanhf(acc[s][j][3] + b1v) * v1;
        }
        pvA += __shfl_xor_sync(0xffffffffu, pvA, 1);
        pvA += __shfl_xor_sync(0xffffffffu, pvA, 2);
        pvB += __shfl_xor_sync(0xffffffffu, pvB, 1);
        pvB += __shfl_xor_sync(0xffffffffu, pvB, 2);
        if ((l & 3) == 0) {
            const int r = mp * 32 + s * 16 + (l >> 2);
            wred[r * 4 + nq]       = pvA;
            wred[(r + 8) * 4 + nq] = pvB;
        }
    }
    __syncthreads();
    if (tid < 64) {
        const float z = wred[tid * 4] + wred[tid * 4 + 1] +
                        wred[tid * 4 + 2] + wred[tid * 4 + 3] + vb[0];
        s_out[row0 + tid] = 1.f / (1.f + expf(-z));
    }
}

// ---------------------------------------------------------------------------
__global__ __launch_bounds__(1024) void stats_kernel(int lvl, int R)
{
    __shared__ float red[1024];
    const float* s = s_buf(lvl);
    const int tid = threadIdx.x;

    float m = -1e30f;
    for (int i = tid; i < R; i += 1024) m = fmaxf(m, s[i]);
    red[tid] = m; __syncthreads();
    for (int off = 512; off; off >>= 1) {
        if (tid < off) red[tid] = fmaxf(red[tid], red[tid + off]);
        __syncthreads();
    }
    const float mx = red[0];
    __syncthreads();

    float sum = 0.f;
    for (int i = tid; i < R; i += 1024) sum += expf(s[i] - mx);
    red[tid] = sum; __syncthreads();
    for (int off = 512; off; off >>= 1) {
        if (tid < off) red[tid] += red[tid + off];
        __syncthreads();
    }
    if (tid == 0) { g_stats[lvl * 2] = mx; g_stats[lvl * 2 + 1] = red[0]; }
}

// ---------------------------------------------------------------------------
// segsum: weighted bag pooling (fp32) + emit fp16 emb for next attention
// ---------------------------------------------------------------------------
__global__ __launch_bounds__(256) void segsum_kernel(int lvl)
{
    __shared__ float ws[16];
    const float* ein  = emb_buf(lvl);
    float*       eout = emb_buf(lvl + 1);
    __half* eoutf = lvl == 0 ? g_emb2f16 : g_emb3f16;
    const float* s    = s_buf(lvl);
    const int bg = blockIdx.x, tid = threadIdx.x;

    if (tid < 16) {
        const float mx = g_stats[lvl * 2];
        const float inv = 1.f / g_stats[lvl * 2 + 1];
        ws[tid] = expf(s[bg * 16 + tid] - mx) * inv;
    }
    __syncthreads();

    const float4* base = (const float4*)(ein + (long)bg * 16 * DIM);
    float4* dst = (float4*)(eout + (long)bg * DIM);
    for (int d = tid; d < DIM / 4; d += 256) {
        float4 a = make_float4(0.f, 0.f, 0.f, 0.f);
        #pragma unroll
        for (int i = 0; i < 16; i++) {
            const float w = ws[i];
            const float4 e = base[i * (DIM / 4) + d];
            a.x += w * e.x; a.y += w * e.y; a.z += w * e.z; a.w += w * e.w;
        }
        dst[d] = a;
        const long eb = (long)bg * DIM + d * 4;
        eoutf[eb + 0] = __float2half(a.x);
        eoutf[eb + 1] = __float2half(a.y);
        eoutf[eb + 2] = __float2half(a.z);
        eoutf[eb + 3] = __float2half(a.w);
    }
}

// ---------------------------------------------------------------------------
__global__ __launch_bounds__(512) void final_kernel(
    const float* __restrict__ clsW, const float* __restrict__ clsb,
    const float* __restrict__ outW, const float* __restrict__ outb,
    float* __restrict__ out)
{
    __shared__ float w3[64];
    __shared__ float outer[DIM];
    __shared__ float red[512];
    const int tid = threadIdx.x;
    const float* s3 = s_buf(2);

    if (tid == 0) {
        float mx = -1e30f;
        for (int i = 0; i < 64; i++) mx = fmaxf(mx, s3[i]);
        float sum = 0.f;
        for (int i = 0; i < 64; i++) { float e = expf(s3[i] - mx); w3[i] = e; sum += e; }
        const float inv = 1.f / sum;
        for (int i = 0; i < 64; i++) w3[i] *= inv;
    }
    __syncthreads();

    for (int d = tid; d < DIM; d += 512) {
        float acc = 0.f;
        #pragma unroll 8
        for (int b2 = 0; b2 < 64; b2++) acc += w3[b2] * g_emb3[b2 * DIM + d];
        outer[d] = acc;
    }
    __syncthreads();

    float acc = 0.f;
    const float* wp = clsW + tid;
    for (int d = 0; d < DIM; d++) acc += outer[d] * wp[d * NCLS];
    red[tid] = (acc + clsb[tid]) * outW[tid];
    __syncthreads();
    for (int off = 256; off; off >>= 1) {
        if (tid < off) red[tid] += red[tid + off];
        __syncthreads();
    }
    if (tid == 0) out[0] = 1.f / (1.f + expf(-(red[0] + outb[0])));
}

// ---------------------------------------------------------------------------
extern "C" void kernel_launch(void* const* d_in, const int* in_sizes, int n_in,
                              void* d_out, int out_size)
{
    const float* x    = (const float*)d_in[0];
    const float* c1w  = (const float*)d_in[1];
    const float* c1b  = (const float*)d_in[2];
    const float* c2w  = (const float*)d_in[3];
    const float* c2b  = (const float*)d_in[4];
    const float* a1W  = (const float*)d_in[5];
    const float* a1b  = (const float*)d_in[6];
    const float* a1v  = (const float*)d_in[7];
    const float* a1vb = (const float*)d_in[8];
    const float* a2W  = (const float*)d_in[9];
    const float* a2b  = (const float*)d_in[10];
    const float* a2v  = (const float*)d_in[11];
    const float* a2vb = (const float*)d_in[12];
    const float* a3W  = (const float*)d_in[13];
    const float* a3b  = (const float*)d_in[14];
    const float* a3v  = (const float*)d_in[15];
    const float* a3vb = (const float*)d_in[16];
    const float* clsW = (const float*)d_in[17];
    const float* clsb = (const float*)d_in[18];
    const float* outW = (const float*)d_in[19];
    const float* outb = (const float*)d_in[20];

    cudaFuncSetAttribute(fused_conv_kernel,
                         cudaFuncAttributeMaxDynamicSharedMemorySize, FC_SMEM);
    cudaFuncSetAttribute(att_mma_kernel,
                         cudaFuncAttributeMaxDynamicSharedMemorySize, ATT_SMEM);

    prep_w2t<<<200, 256>>>(c2w);
    prep_awt_all<<<3072, 256>>>(a1W, a2W, a3W);

    fused_conv_kernel<<<N_INST / 2, 256, FC_SMEM>>>(x, c1w, c1b, c2b);

    att_mma_kernel<<<N_INST / 64, 256, ATT_SMEM>>>(0, a1b, a1v, a1vb);
    stats_kernel<<<1, 1024>>>(0, N_INST);
    segsum_kernel<<<NB1, 256>>>(0);

    att_mma_kernel<<<NB1 / 64, 256, ATT_SMEM>>>(1, a2b, a2v, a2vb);
    stats_kernel<<<1, 1024>>>(1, NB1);
    segsum_kernel<<<NB2, 256>>>(1);

    att_mma_kernel<<<NB2 / 64, 256, ATT_SMEM>>>(2, a3b, a3v, a3vb);
    final_kernel<<<1, 512>>>(clsW, clsb, outW, outb, (float*)d_out);
}